// round 1
// baseline (speedup 1.0000x reference)
#include <cuda_runtime.h>
#include <cstddef>

// Problem constants
#define S_TOTAL   5120          // B*N*O sites
#define FDIM      256
#define HH        4
#define DD        64
#define DFFDIM    1024
#define PATCH     6400          // K*K*F = 25*256
#define CENTER    3072          // (2*5+2)*256
#define NB_STAT   64            // partial blocks per batch
#define BATCH_ELEMS 327680      // 1280*256
#define EPSLN     1e-5f

// ---------------- scratch (static __device__, no allocation) ----------------
__device__ float g_qc[S_TOTAL * FDIM];
__device__ float g_qk[S_TOTAL * HH * FDIM];
__device__ float g_xbar[S_TOTAL * HH * FDIM];
__device__ float g_merged[S_TOTAL * FDIM];
__device__ float g_att[S_TOTAL * FDIM];
__device__ float g_out1[S_TOTAL * FDIM];
__device__ float g_h1[S_TOTAL * DFFDIM];
__device__ float g_y[S_TOTAL * FDIM];
__device__ float g_WkT[HH * FDIM * DD];     // WkT[h][f][d] = Wk[h*64+d][f]
__device__ float2 g_part[4 * NB_STAT];
__device__ float g_mu[4];
__device__ float g_rsd[4];

// ---------------- prologue: transpose Wk per head ----------------
__global__ void transpose_wk_kernel(const float* __restrict__ Wk) {
    int idx = blockIdx.x * blockDim.x + threadIdx.x;   // 65536 total
    int h = idx >> 14;
    int f = (idx >> 6) & 255;
    int d = idx & 63;
    g_WkT[idx] = Wk[(h * 64 + d) * 256 + f];
}

// ---------------- generic tiled fp32 GEMM: C[m,n] = sum_k A[m,k]*B[n,k] ----
// BM=BN=64, BK=16, 256 threads, 4x4 micro-tile per thread.
template<bool RELU, bool BIAS, bool RES>
__global__ void gemm_kernel(const float* __restrict__ A, int lda,
                            const float* __restrict__ B, int ldb,
                            float* __restrict__ C, int ldc,
                            const float* __restrict__ bias,
                            const float* __restrict__ Res, int ldr,
                            int Ktot) {
    __shared__ __align__(16) float As[16][64];
    __shared__ __align__(16) float Bs[16][64];

    const int tid = threadIdx.x;
    const int m0 = blockIdx.y * 64;
    const int n0 = blockIdx.x * 64;

    const int lr = tid >> 2;            // 0..63 loader row
    const int kq = (tid & 3) * 4;       // 0,4,8,12 loader k quad
    const float* Ag = A + (size_t)(m0 + lr) * lda + kq;
    const float* Bg = B + (size_t)(n0 + lr) * ldb + kq;

    const int ty = tid >> 4, tx = tid & 15;
    const int my = ty * 4, nx = tx * 4;

    float acc[4][4] = {};

    for (int k0 = 0; k0 < Ktot; k0 += 16) {
        float4 a4 = *(const float4*)(Ag + k0);
        float4 b4 = *(const float4*)(Bg + k0);
        __syncthreads();
        As[kq + 0][lr] = a4.x; As[kq + 1][lr] = a4.y;
        As[kq + 2][lr] = a4.z; As[kq + 3][lr] = a4.w;
        Bs[kq + 0][lr] = b4.x; Bs[kq + 1][lr] = b4.y;
        Bs[kq + 2][lr] = b4.z; Bs[kq + 3][lr] = b4.w;
        __syncthreads();
#pragma unroll
        for (int kk = 0; kk < 16; kk++) {
            const float4 av = *(const float4*)&As[kk][my];
            const float4 bv = *(const float4*)&Bs[kk][nx];
            float a_[4] = {av.x, av.y, av.z, av.w};
            float b_[4] = {bv.x, bv.y, bv.z, bv.w};
#pragma unroll
            for (int i = 0; i < 4; i++)
#pragma unroll
                for (int j = 0; j < 4; j++)
                    acc[i][j] = fmaf(a_[i], b_[j], acc[i][j]);
        }
    }

    float4 bb = make_float4(0.f, 0.f, 0.f, 0.f);
    if (BIAS) bb = *(const float4*)(bias + n0 + nx);
#pragma unroll
    for (int i = 0; i < 4; i++) {
        float4 v;
        v.x = acc[i][0] + bb.x;
        v.y = acc[i][1] + bb.y;
        v.z = acc[i][2] + bb.z;
        v.w = acc[i][3] + bb.w;
        if (RELU) {
            v.x = fmaxf(v.x, 0.f); v.y = fmaxf(v.y, 0.f);
            v.z = fmaxf(v.z, 0.f); v.w = fmaxf(v.w, 0.f);
        }
        if (RES) {
            const float4 r4 = *(const float4*)(Res + (size_t)(m0 + my + i) * ldr + n0 + nx);
            v.x += r4.x; v.y += r4.y; v.z += r4.z; v.w += r4.w;
        }
        *(float4*)(C + (size_t)(m0 + my + i) * ldc + n0 + nx) = v;
    }
}

// ---------------- fused attention: scores -> softmax -> xbar ----------------
// one block per site; reads the whole 25x256 patch once (memory-bound kernel)
__global__ void attn_kernel(const float* __restrict__ x,
                            const float* __restrict__ qk,
                            float* __restrict__ xbar) {
    __shared__ float xs[PATCH];        // 25.6 KB
    __shared__ float qs[HH * FDIM];    // 4 KB
    __shared__ float scr[128];
    __shared__ float wts[128];

    const int s = blockIdx.x;
    const int tid = threadIdx.x;

    const float4* xg = (const float4*)(x + (size_t)s * PATCH);
    for (int i = tid; i < PATCH / 4; i += 256) ((float4*)xs)[i] = xg[i];
    ((float4*)qs)[tid] = ((const float4*)(qk + (size_t)s * 1024))[tid];
    __syncthreads();

    // 100 dot products (h,p), one warp handles every 8th
    const int w = tid >> 5, l = tid & 31;
    for (int d = w; d < 100; d += 8) {
        const int h = d / 25, p = d % 25;
        const float* xp = xs + p * FDIM;
        const float* qh = qs + h * FDIM;
        float acc = 0.f;
#pragma unroll
        for (int f = l; f < FDIM; f += 32) acc += qh[f] * xp[f];
#pragma unroll
        for (int o = 16; o; o >>= 1) acc += __shfl_xor_sync(0xffffffffu, acc, o);
        if (l == 0) scr[d] = acc * 0.125f;   // 1/sqrt(64)
    }
    __syncthreads();

    // per-head softmax over 25 (4 threads; trivial work)
    if (tid < 4) {
        float mx = -1e30f;
        for (int p = 0; p < 25; p++) mx = fmaxf(mx, scr[tid * 25 + p]);
        float e[25];
        float sum = 0.f;
        for (int p = 0; p < 25; p++) { e[p] = expf(scr[tid * 25 + p] - mx); sum += e[p]; }
        const float inv = 1.f / sum;
        for (int p = 0; p < 25; p++) wts[tid * 25 + p] = e[p] * inv;
    }
    __syncthreads();

    // xbar[h][f] = sum_p w[h][p] * x[p][f]
    float acc[HH] = {0.f, 0.f, 0.f, 0.f};
    for (int p = 0; p < 25; p++) {
        const float v = xs[p * FDIM + tid];
#pragma unroll
        for (int h = 0; h < HH; h++) acc[h] += wts[h * 25 + p] * v;
    }
    float* ob = xbar + (size_t)s * 1024;
#pragma unroll
    for (int h = 0; h < HH; h++) ob[h * FDIM + tid] = acc[h];
}

// ---------------- per-batch LayerNorm (deterministic 2-level reduce) --------
__global__ void stats_kernel(const float* __restrict__ src) {
    const int bid = blockIdx.x;            // 0..255
    const int b = bid >> 6, i = bid & 63;
    const float* p = src + (size_t)b * BATCH_ELEMS + i * (BATCH_ELEMS / NB_STAT);
    float s = 0.f, ss = 0.f;
    for (int j = threadIdx.x; j < BATCH_ELEMS / NB_STAT; j += 256) {
        const float v = p[j];
        s += v; ss += v * v;
    }
    __shared__ float rs_[256], rss_[256];
    rs_[threadIdx.x] = s; rss_[threadIdx.x] = ss;
    __syncthreads();
    for (int o = 128; o; o >>= 1) {
        if (threadIdx.x < o) {
            rs_[threadIdx.x] += rs_[threadIdx.x + o];
            rss_[threadIdx.x] += rss_[threadIdx.x + o];
        }
        __syncthreads();
    }
    if (threadIdx.x == 0) g_part[bid] = make_float2(rs_[0], rss_[0]);
}

__global__ void finalize_kernel() {
    const int b = threadIdx.x;
    if (b < 4) {
        float s = 0.f, ss = 0.f;
        for (int i = 0; i < NB_STAT; i++) {
            const float2 v = g_part[b * NB_STAT + i];
            s += v.x; ss += v.y;
        }
        const float mu = s / (float)BATCH_ELEMS;
        const float var = ss / (float)BATCH_ELEMS - mu * mu;
        g_mu[b] = mu;
        g_rsd[b] = rsqrtf(var + EPSLN);
    }
}

__global__ void ln_apply_kernel(const float* __restrict__ src,
                                const float* __restrict__ w,
                                const float* __restrict__ bb,
                                float* __restrict__ dst) {
    const int i = blockIdx.x * 256 + threadIdx.x;
    const int b = i / BATCH_ELEMS;
    const int r = i - b * BATCH_ELEMS;
    dst[i] = (src[i] - g_mu[b]) * g_rsd[b] * w[r] + bb[r];
}

// ---------------- launch ----------------------------------------------------
extern "C" void kernel_launch(void* const* d_in, const int* in_sizes, int n_in,
                              void* d_out, int out_size) {
    const float* x    = (const float*)d_in[0];
    const float* Wq   = (const float*)d_in[1];
    const float* bq   = (const float*)d_in[2];
    const float* Wk   = (const float*)d_in[3];
    // bk (d_in[4]) is provably irrelevant: constant shift under softmax
    const float* Wv   = (const float*)d_in[5];
    const float* bv   = (const float*)d_in[6];
    const float* Wf   = (const float*)d_in[7];
    const float* bf   = (const float*)d_in[8];
    const float* ln1w = (const float*)d_in[9];
    const float* ln1b = (const float*)d_in[10];
    const float* ln2w = (const float*)d_in[11];
    const float* ln2b = (const float*)d_in[12];
    const float* W1   = (const float*)d_in[13];
    const float* b1   = (const float*)d_in[14];
    const float* W2   = (const float*)d_in[15];
    const float* b2   = (const float*)d_in[16];
    float* out = (float*)d_out;

    float *qc, *qkb, *xbar, *merged, *att, *out1, *h1, *ybuf, *wkt;
    cudaGetSymbolAddress((void**)&qc,     g_qc);
    cudaGetSymbolAddress((void**)&qkb,    g_qk);
    cudaGetSymbolAddress((void**)&xbar,   g_xbar);
    cudaGetSymbolAddress((void**)&merged, g_merged);
    cudaGetSymbolAddress((void**)&att,    g_att);
    cudaGetSymbolAddress((void**)&out1,   g_out1);
    cudaGetSymbolAddress((void**)&h1,     g_h1);
    cudaGetSymbolAddress((void**)&ybuf,   g_y);
    cudaGetSymbolAddress((void**)&wkt,    g_WkT);

    // prologue: WkT[h][f][d]
    transpose_wk_kernel<<<256, 256>>>(Wk);

    // qc = Xcenter @ Wq^T + bq           (5120 x 256, K=256)
    gemm_kernel<false, true, false><<<dim3(4, 80), 256>>>(
        x + CENTER, PATCH, Wq, 256, qc, 256, bq, nullptr, 0, 256);

    // qk_h = qc_h @ WkT_h                (5120 x 256, K=64) x 4 heads
    for (int h = 0; h < HH; h++)
        gemm_kernel<false, false, false><<<dim3(4, 80), 256>>>(
            qc + h * 64, 256, wkt + h * (256 * 64), 64,
            qkb + h * 256, 1024, nullptr, nullptr, 0, 64);

    // fused scores / softmax / weighted-average
    attn_kernel<<<S_TOTAL, 256>>>(x, qkb, xbar);

    // merged_h = xbar_h @ Wv_h^T + bv_h  (5120 x 64, K=256) x 4 heads
    for (int h = 0; h < HH; h++)
        gemm_kernel<false, true, false><<<dim3(1, 80), 256>>>(
            xbar + h * 256, 1024, Wv + h * 64 * 256, 256,
            merged + h * 64, 256, bv + h * 64, nullptr, 0, 256);

    // attent = merged @ Wf^T + bf        (5120 x 256, K=256)
    gemm_kernel<false, true, false><<<dim3(4, 80), 256>>>(
        merged, 256, Wf, 256, att, 256, bf, nullptr, 0, 256);

    // LayerNorm1 (per-batch over N,O,F)
    stats_kernel<<<4 * NB_STAT, 256>>>(att);
    finalize_kernel<<<1, 32>>>();
    ln_apply_kernel<<<S_TOTAL, 256>>>(att, ln1w, ln1b, out1);

    // FFN1: h1 = relu(out1 @ W1^T + b1)  (5120 x 1024, K=256)
    gemm_kernel<true, true, false><<<dim3(16, 80), 256>>>(
        out1, 256, W1, 256, h1, 1024, b1, nullptr, 0, 256);

    // FFN2: y = h1 @ W2^T + b2 + out1    (5120 x 256, K=1024)
    gemm_kernel<false, true, true><<<dim3(4, 80), 256>>>(
        h1, 1024, W2, 1024, ybuf, 256, b2, out1, 256, 1024);

    // LayerNorm2 -> output
    stats_kernel<<<4 * NB_STAT, 256>>>(ybuf);
    finalize_kernel<<<1, 32>>>();
    ln_apply_kernel<<<S_TOTAL, 256>>>(ybuf, ln2w, ln2b, out);
}

// round 5
// speedup vs baseline: 1.3093x; 1.3093x over previous
#include <cuda_runtime.h>
#include <cuda_bf16.h>
#include <mma.h>
#include <cstdint>
#include <cstddef>

using namespace nvcuda;
typedef __nv_bfloat16 bf16;

#define S_TOTAL     5120
#define EPSLN       1e-5f
#define BATCH_ELEMS 327680
#define NB_STAT     64

// ===================== scratch (static __device__) ==========================
__device__ float g_qk  [S_TOTAL * 1024];
__device__ float g_att [S_TOTAL * 256];
__device__ float g_out1[S_TOTAL * 256];
__device__ float g_y   [S_TOTAL * 256];

__device__ bf16 g_xc_h[S_TOTAL * 256],  g_xc_l[S_TOTAL * 256];
__device__ bf16 g_qc_h[S_TOTAL * 256],  g_qc_l[S_TOTAL * 256];
__device__ bf16 g_xb_h[S_TOTAL * 1024], g_xb_l[S_TOTAL * 1024];
__device__ bf16 g_mg_h[S_TOTAL * 256],  g_mg_l[S_TOTAL * 256];
__device__ bf16 g_o1_h[S_TOTAL * 256],  g_o1_l[S_TOTAL * 256];
__device__ bf16 g_h1_h[S_TOTAL * 1024], g_h1_l[S_TOTAL * 1024];

__device__ bf16 g_Wq_h[65536],  g_Wq_l[65536];
__device__ bf16 g_Wkt_h[65536], g_Wkt_l[65536];
__device__ bf16 g_Wv_h[65536],  g_Wv_l[65536];
__device__ bf16 g_Wf_h[65536],  g_Wf_l[65536];
__device__ bf16 g_W1_h[262144], g_W1_l[262144];
__device__ bf16 g_W2_h[262144], g_W2_l[262144];

__device__ float2 g_part[4 * NB_STAT];
__device__ float g_mu[4];
__device__ float g_rsd[4];

// ===================== conversion kernels ===================================
__device__ __forceinline__ void split_store(float v, bf16* hi, bf16* lo, size_t i) {
    bf16 h = __float2bfloat16(v);
    hi[i] = h;
    lo[i] = __float2bfloat16(v - __bfloat162float(h));
}

__global__ void cvt_kernel(const float* __restrict__ s, bf16* __restrict__ hi,
                           bf16* __restrict__ lo, int n) {
    int i = blockIdx.x * 256 + threadIdx.x;
    if (i < n) split_store(s[i], hi, lo, i);
}

// WkT[h][f][d] = Wk[h*64+d][f]
__global__ void wkt_cvt_kernel(const float* __restrict__ Wk) {
    int idx = blockIdx.x * 256 + threadIdx.x;     // 65536
    int h = idx >> 14, f = (idx >> 6) & 255, d = idx & 63;
    split_store(Wk[(h * 64 + d) * 256 + f], g_Wkt_h, g_Wkt_l, idx);
}

// gather patch-center rows of x
__global__ void center_cvt_kernel(const float* __restrict__ x) {
    int s = blockIdx.x, f = threadIdx.x;
    split_store(x[(size_t)s * 6400 + 3072 + f], g_xc_h, g_xc_l, (size_t)s * 256 + f);
}

// ===================== wmma split-bf16 GEMM =================================
// C[m,n] = sum_k A[m,k]*B[n,k];  BM=128, BN=64, BK=32, 256 threads (8 warps).
// Warp grid 4(M) x 2(N); warp tile 32x32 -> 2x2 wmma 16x16x16 fragments.
// Split-bf16 3-product: C += Ahi*Bhi + Ahi*Blo + Alo*Bhi (fp32 accum).
#define LDT 40   // padded smem leading dim (bf16 elems); row = 80B, 16B aligned

template<bool RELU, bool BIAS, bool RES, bool WF32, bool WBF16>
__global__ __launch_bounds__(256) void mm_kernel(
    const bf16* __restrict__ Ahi, const bf16* __restrict__ Alo, int lda, int aHead,
    const bf16* __restrict__ Bhi, const bf16* __restrict__ Blo, int ldb, int bHead,
    float* __restrict__ Cf, bf16* __restrict__ Chi, bf16* __restrict__ Clo,
    int ldc, int cHead,
    const float* __restrict__ bias, int biasHead,
    const float* __restrict__ Res, int ldr, int Ktot)
{
    __shared__ union {
        struct {
            bf16 Ah[128 * LDT];
            bf16 Al[128 * LDT];
            bf16 Bh[64 * LDT];
            bf16 Bl[64 * LDT];
        } t;
        float cout[128 * 64];
    } sm;

    const int tid = threadIdx.x;
    const int wid = tid >> 5;
    const int wm = wid >> 1, wn = wid & 1;         // warp grid 4x2
    const int m0 = blockIdx.y * 128, n0 = blockIdx.x * 64;
    const int z = blockIdx.z;

    Ahi += (size_t)z * aHead; Alo += (size_t)z * aHead;
    Bhi += (size_t)z * bHead; Blo += (size_t)z * bHead;

    wmma::fragment<wmma::accumulator, 16, 16, 16, float> cacc[2][2];
#pragma unroll
    for (int i = 0; i < 2; i++)
#pragma unroll
        for (int j = 0; j < 2; j++) wmma::fill_fragment(cacc[i][j], 0.0f);

    // loader indices: A tiles are 128x32 -> 512 uint4 per matrix (2/thread)
    const int ar0 = tid >> 2,        ac0 = (tid & 3) * 8;        // chunk 0
    const int ar1 = (tid + 256) >> 2, ac1 = (tid & 3) * 8;       // chunk 1
    const int br  = tid >> 2,        bc  = (tid & 3) * 8;        // B: 64x32, 1/thread

    for (int k0 = 0; k0 < Ktot; k0 += 32) {
        // stage global -> regs
        uint4 a0h = *(const uint4*)(Ahi + (size_t)(m0 + ar0) * lda + k0 + ac0);
        uint4 a0l = *(const uint4*)(Alo + (size_t)(m0 + ar0) * lda + k0 + ac0);
        uint4 a1h = *(const uint4*)(Ahi + (size_t)(m0 + ar1) * lda + k0 + ac1);
        uint4 a1l = *(const uint4*)(Alo + (size_t)(m0 + ar1) * lda + k0 + ac1);
        uint4 b0h = *(const uint4*)(Bhi + (size_t)(n0 + br) * ldb + k0 + bc);
        uint4 b0l = *(const uint4*)(Blo + (size_t)(n0 + br) * ldb + k0 + bc);
        __syncthreads();
        *(uint4*)(sm.t.Ah + ar0 * LDT + ac0) = a0h;
        *(uint4*)(sm.t.Al + ar0 * LDT + ac0) = a0l;
        *(uint4*)(sm.t.Ah + ar1 * LDT + ac1) = a1h;
        *(uint4*)(sm.t.Al + ar1 * LDT + ac1) = a1l;
        *(uint4*)(sm.t.Bh + br * LDT + bc)   = b0h;
        *(uint4*)(sm.t.Bl + br * LDT + bc)   = b0l;
        __syncthreads();

#pragma unroll
        for (int ks = 0; ks < 32; ks += 16) {
            wmma::fragment<wmma::matrix_a, 16, 16, 16, bf16, wmma::row_major> ah[2], al[2];
            wmma::fragment<wmma::matrix_b, 16, 16, 16, bf16, wmma::col_major> bh[2], bl[2];
#pragma unroll
            for (int i = 0; i < 2; i++) {
                const int row = wm * 32 + i * 16;
                wmma::load_matrix_sync(ah[i], sm.t.Ah + row * LDT + ks, LDT);
                wmma::load_matrix_sync(al[i], sm.t.Al + row * LDT + ks, LDT);
            }
#pragma unroll
            for (int j = 0; j < 2; j++) {
                const int col = wn * 32 + j * 16;
                wmma::load_matrix_sync(bh[j], sm.t.Bh + col * LDT + ks, LDT);
                wmma::load_matrix_sync(bl[j], sm.t.Bl + col * LDT + ks, LDT);
            }
#pragma unroll
            for (int i = 0; i < 2; i++)
#pragma unroll
                for (int j = 0; j < 2; j++) {
                    wmma::mma_sync(cacc[i][j], ah[i], bh[j], cacc[i][j]);
                    wmma::mma_sync(cacc[i][j], ah[i], bl[j], cacc[i][j]);
                    wmma::mma_sync(cacc[i][j], al[i], bh[j], cacc[i][j]);
                }
        }
    }

    // stage accumulators through SMEM
    __syncthreads();
#pragma unroll
    for (int i = 0; i < 2; i++)
#pragma unroll
        for (int j = 0; j < 2; j++)
            wmma::store_matrix_sync(
                sm.cout + (wm * 32 + i * 16) * 64 + wn * 32 + j * 16,
                cacc[i][j], 64, wmma::mem_row_major);
    __syncthreads();

    // postprocess: each thread handles one half-row of 32 floats
    const int r = tid >> 1, ch = (tid & 1) * 32;
    const int m = m0 + r;
    if (BIAS) bias += (size_t)z * biasHead;
    float* cf = nullptr; bf16* chi = nullptr; bf16* clo = nullptr;
    if (WF32)  cf  = Cf  + (size_t)z * cHead + (size_t)m * ldc + n0 + ch;
    if (WBF16) { chi = Chi + (size_t)z * cHead + (size_t)m * ldc + n0 + ch;
                 clo = Clo + (size_t)z * cHead + (size_t)m * ldc + n0 + ch; }

#pragma unroll
    for (int q = 0; q < 8; q++) {
        float4 v = *(float4*)(sm.cout + r * 64 + ch + q * 4);
        if (BIAS) {
            const float4 b4 = *(const float4*)(bias + n0 + ch + q * 4);
            v.x += b4.x; v.y += b4.y; v.z += b4.z; v.w += b4.w;
        }
        if (RELU) {
            v.x = fmaxf(v.x, 0.f); v.y = fmaxf(v.y, 0.f);
            v.z = fmaxf(v.z, 0.f); v.w = fmaxf(v.w, 0.f);
        }
        if (RES) {
            const float4 r4 = *(const float4*)(Res + (size_t)m * ldr + n0 + ch + q * 4);
            v.x += r4.x; v.y += r4.y; v.z += r4.z; v.w += r4.w;
        }
        if (WF32) *(float4*)(cf + q * 4) = v;
        if (WBF16) {
            float vv[4] = {v.x, v.y, v.z, v.w};
#pragma unroll
            for (int j = 0; j < 4; j += 2) {
                bf16 h0 = __float2bfloat16(vv[j]);
                bf16 h1 = __float2bfloat16(vv[j + 1]);
                __nv_bfloat162 hp; hp.x = h0; hp.y = h1;
                __nv_bfloat162 lp;
                lp.x = __float2bfloat16(vv[j]     - __bfloat162float(h0));
                lp.y = __float2bfloat16(vv[j + 1] - __bfloat162float(h1));
                *(__nv_bfloat162*)(chi + q * 4 + j) = hp;
                *(__nv_bfloat162*)(clo + q * 4 + j) = lp;
            }
        }
    }
}

// ===================== fused attention (fp32, memory-bound) =================
__global__ void attn_kernel(const float* __restrict__ x,
                            const float* __restrict__ qk) {
    __shared__ float xs[6400];
    __shared__ float qs[1024];
    __shared__ float scr[128];
    __shared__ float wts[128];

    const int s = blockIdx.x;
    const int tid = threadIdx.x;

    const float4* xg = (const float4*)(x + (size_t)s * 6400);
    for (int i = tid; i < 1600; i += 256) ((float4*)xs)[i] = xg[i];
    ((float4*)qs)[tid] = ((const float4*)(qk + (size_t)s * 1024))[tid];
    __syncthreads();

    const int w = tid >> 5, l = tid & 31;
    for (int d = w; d < 100; d += 8) {
        const int h = d / 25, p = d % 25;
        const float* xp = xs + p * 256;
        const float* qh = qs + h * 256;
        float acc = 0.f;
#pragma unroll
        for (int f = l; f < 256; f += 32) acc += qh[f] * xp[f];
#pragma unroll
        for (int o = 16; o; o >>= 1) acc += __shfl_xor_sync(0xffffffffu, acc, o);
        if (l == 0) scr[d] = acc * 0.125f;
    }
    __syncthreads();

    if (tid < 4) {
        float mx = -1e30f;
        for (int p = 0; p < 25; p++) mx = fmaxf(mx, scr[tid * 25 + p]);
        float e[25], sum = 0.f;
        for (int p = 0; p < 25; p++) { e[p] = expf(scr[tid * 25 + p] - mx); sum += e[p]; }
        const float inv = 1.f / sum;
        for (int p = 0; p < 25; p++) wts[tid * 25 + p] = e[p] * inv;
    }
    __syncthreads();

    float acc[4] = {0.f, 0.f, 0.f, 0.f};
    for (int p = 0; p < 25; p++) {
        const float v = xs[p * 256 + tid];
#pragma unroll
        for (int h = 0; h < 4; h++) acc[h] += wts[h * 25 + p] * v;
    }
#pragma unroll
    for (int h = 0; h < 4; h++)
        split_store(acc[h], g_xb_h, g_xb_l, (size_t)s * 1024 + h * 256 + tid);
}

// ===================== per-batch LayerNorm ==================================
__global__ void stats_kernel(const float* __restrict__ src) {
    const int bid = blockIdx.x;
    const int b = bid >> 6, i = bid & 63;
    const float* p = src + (size_t)b * BATCH_ELEMS + i * (BATCH_ELEMS / NB_STAT);
    float s = 0.f, ss = 0.f;
    for (int j = threadIdx.x; j < BATCH_ELEMS / NB_STAT; j += 256) {
        const float v = p[j];
        s += v; ss += v * v;
    }
    __shared__ float rs_[256], rss_[256];
    rs_[threadIdx.x] = s; rss_[threadIdx.x] = ss;
    __syncthreads();
    for (int o = 128; o; o >>= 1) {
        if (threadIdx.x < o) {
            rs_[threadIdx.x] += rs_[threadIdx.x + o];
            rss_[threadIdx.x] += rss_[threadIdx.x + o];
        }
        __syncthreads();
    }
    if (threadIdx.x == 0) g_part[bid] = make_float2(rs_[0], rss_[0]);
}

__global__ void finalize_kernel() {
    const int b = threadIdx.x;
    if (b < 4) {
        float s = 0.f, ss = 0.f;
        for (int i = 0; i < NB_STAT; i++) {
            const float2 v = g_part[b * NB_STAT + i];
            s += v.x; ss += v.y;
        }
        const float mu = s / (float)BATCH_ELEMS;
        const float var = ss / (float)BATCH_ELEMS - mu * mu;
        g_mu[b] = mu;
        g_rsd[b] = rsqrtf(var + EPSLN);
    }
}

__global__ void ln_apply_kernel(const float* __restrict__ src,
                                const float* __restrict__ w,
                                const float* __restrict__ bb,
                                float* __restrict__ dst,
                                bf16* __restrict__ dhi, bf16* __restrict__ dlo) {
    const int i = blockIdx.x * 256 + threadIdx.x;
    const int b = i / BATCH_ELEMS;
    const int r = i - b * BATCH_ELEMS;
    const float v = (src[i] - g_mu[b]) * g_rsd[b] * w[r] + bb[r];
    dst[i] = v;
    if (dhi) split_store(v, dhi, dlo, i);
}

// ===================== launch ===============================================
#define SYM(T, p, s) T* p; { void* t_; cudaGetSymbolAddress(&t_, s); p = (T*)t_; }

extern "C" void kernel_launch(void* const* d_in, const int* in_sizes, int n_in,
                              void* d_out, int out_size) {
    const float* x    = (const float*)d_in[0];
    const float* Wq   = (const float*)d_in[1];
    const float* bq   = (const float*)d_in[2];
    const float* Wk   = (const float*)d_in[3];
    // bk (d_in[4]) is provably irrelevant: constant shift under softmax
    const float* Wv   = (const float*)d_in[5];
    const float* bv   = (const float*)d_in[6];
    const float* Wf   = (const float*)d_in[7];
    const float* bf_  = (const float*)d_in[8];
    const float* ln1w = (const float*)d_in[9];
    const float* ln1b = (const float*)d_in[10];
    const float* ln2w = (const float*)d_in[11];
    const float* ln2b = (const float*)d_in[12];
    const float* W1   = (const float*)d_in[13];
    const float* b1   = (const float*)d_in[14];
    const float* W2   = (const float*)d_in[15];
    const float* b2   = (const float*)d_in[16];
    float* out = (float*)d_out;

    SYM(float, qkp,  g_qk);   SYM(float, attp, g_att);
    SYM(float, o1p,  g_out1); SYM(float, yp,   g_y);
    SYM(bf16, xch, g_xc_h);   SYM(bf16, xcl, g_xc_l);
    SYM(bf16, qch, g_qc_h);   SYM(bf16, qcl, g_qc_l);
    SYM(bf16, xbh, g_xb_h);   SYM(bf16, xbl, g_xb_l);
    SYM(bf16, mgh, g_mg_h);   SYM(bf16, mgl, g_mg_l);
    SYM(bf16, o1h, g_o1_h);   SYM(bf16, o1l, g_o1_l);
    SYM(bf16, h1h, g_h1_h);   SYM(bf16, h1l, g_h1_l);
    SYM(bf16, wqh, g_Wq_h);   SYM(bf16, wql, g_Wq_l);
    SYM(bf16, wkh, g_Wkt_h);  SYM(bf16, wkl, g_Wkt_l);
    SYM(bf16, wvh, g_Wv_h);   SYM(bf16, wvl, g_Wv_l);
    SYM(bf16, wfh, g_Wf_h);   SYM(bf16, wfl, g_Wf_l);
    SYM(bf16, w1h, g_W1_h);   SYM(bf16, w1l, g_W1_l);
    SYM(bf16, w2h, g_W2_h);   SYM(bf16, w2l, g_W2_l);

    // -- convert weights + x-center to split bf16
    cvt_kernel<<<256, 256>>>(Wq, wqh, wql, 65536);
    cvt_kernel<<<256, 256>>>(Wv, wvh, wvl, 65536);
    cvt_kernel<<<256, 256>>>(Wf, wfh, wfl, 65536);
    cvt_kernel<<<1024, 256>>>(W1, w1h, w1l, 262144);
    cvt_kernel<<<1024, 256>>>(W2, w2h, w2l, 262144);
    wkt_cvt_kernel<<<256, 256>>>(Wk);
    center_cvt_kernel<<<S_TOTAL, 256>>>(x);

    // qc = Xc @ Wq^T + bq  -> bf16 split        (M=5120, N=256, K=256)
    mm_kernel<false, true, false, false, true><<<dim3(4, 40, 1), 256>>>(
        xch, xcl, 256, 0, wqh, wql, 256, 0,
        nullptr, qch, qcl, 256, 0, bq, 0, nullptr, 0, 256);

    // qk_h = qc_h @ WkT_h -> fp32               (per head: N=256, K=64)
    mm_kernel<false, false, false, true, false><<<dim3(4, 40, 4), 256>>>(
        qch, qcl, 256, 64, wkh, wkl, 64, 16384,
        qkp, nullptr, nullptr, 1024, 256, nullptr, 0, nullptr, 0, 64);

    // fused scores/softmax/weighted-avg -> xbar bf16 split
    attn_kernel<<<S_TOTAL, 256>>>(x, qkp);

    // merged_h = xbar_h @ Wv_h^T + bv_h -> bf16 (per head: N=64, K=256)
    mm_kernel<false, true, false, false, true><<<dim3(1, 40, 4), 256>>>(
        xbh, xbl, 1024, 256, wvh, wvl, 256, 16384,
        nullptr, mgh, mgl, 256, 64, bv, 64, nullptr, 0, 256);

    // attent = merged @ Wf^T + bf -> fp32       (N=256, K=256)
    mm_kernel<false, true, false, true, false><<<dim3(4, 40, 1), 256>>>(
        mgh, mgl, 256, 0, wfh, wfl, 256, 0,
        attp, nullptr, nullptr, 256, 0, bf_, 0, nullptr, 0, 256);

    // LayerNorm1 -> out1 fp32 + bf16 split
    stats_kernel<<<4 * NB_STAT, 256>>>(attp);
    finalize_kernel<<<1, 32>>>();
    ln_apply_kernel<<<S_TOTAL, 256>>>(attp, ln1w, ln1b, o1p, o1h, o1l);

    // FFN1: h1 = relu(out1 @ W1^T + b1) -> bf16 (N=1024, K=256)
    mm_kernel<true, true, false, false, true><<<dim3(16, 40, 1), 256>>>(
        o1h, o1l, 256, 0, w1h, w1l, 256, 0,
        nullptr, h1h, h1l, 1024, 0, b1, 0, nullptr, 0, 256);

    // FFN2: y = h1 @ W2^T + b2 + out1 -> fp32   (N=256, K=1024)
    mm_kernel<false, true, true, true, false><<<dim3(4, 40, 1), 256>>>(
        h1h, h1l, 1024, 0, w2h, w2l, 1024, 0,
        yp, nullptr, nullptr, 256, 0, b2, 0, o1p, 256, 1024);

    // LayerNorm2 -> out
    stats_kernel<<<4 * NB_STAT, 256>>>(yp);
    finalize_kernel<<<1, 32>>>();
    ln_apply_kernel<<<S_TOTAL, 256>>>(yp, ln2w, ln2b, out, nullptr, nullptr);
}